// round 10
// baseline (speedup 1.0000x reference)
#include <cuda_runtime.h>
#include <cuda_bf16.h>
#include <math.h>
#include <stdint.h>

#define B_SZ  4
#define NSEQ  1024
#define DIMM  2048
#define KDIM  2048
#define NH    16
#define NKV   4
#define DH    128
#define MTOT  (B_SZ * NSEQ)

// ---------------- scratch (device globals: no allocation allowed) ----------
__device__ float g_Qh[B_SZ * NH  * NSEQ * DH];     // fp32 [b,h,n,d]
__device__ float g_Kh[B_SZ * NKV * NSEQ * DH];
__device__ float g_Vh[B_SZ * NKV * NSEQ * DH];
__device__ __nv_bfloat16 g_xhi[MTOT * KDIM], g_xlo[MTOT * KDIM];
__device__ __nv_bfloat16 g_Wqh[2048 * KDIM], g_Wql[2048 * KDIM];   // W^T [n][k]
__device__ __nv_bfloat16 g_Wkh[512  * KDIM], g_Wkl[512  * KDIM];
__device__ __nv_bfloat16 g_Wvh[512  * KDIM], g_Wvl[512  * KDIM];
__device__ __nv_bfloat16 g_Woh[2048 * KDIM], g_Wol[2048 * KDIM];
__device__ __nv_bfloat16 g_Ohi[MTOT * DIMM], g_Olo[MTOT * DIMM];
__device__ __nv_bfloat16 g_Qbh[B_SZ * NH  * NSEQ * DH], g_Qbl[B_SZ * NH  * NSEQ * DH];
__device__ __nv_bfloat16 g_Kbh[B_SZ * NKV * NSEQ * DH], g_Kbl[B_SZ * NKV * NSEQ * DH];
__device__ __nv_bfloat16 g_Vbh[B_SZ * NKV * NSEQ * DH], g_Vbl[B_SZ * NKV * NSEQ * DH];
__device__ float g_cs[NSEQ * 64 * 2];              // rope cos/sin table

// ---------------- helpers ---------------------------------------------------
__device__ __forceinline__ uint32_t cvta_s(const void* p) {
    uint32_t a;
    asm("{ .reg .u64 t; cvta.to.shared.u64 t, %1; cvt.u32.u64 %0, t; }"
        : "=r"(a) : "l"(p));
    return a;
}
__device__ __forceinline__ void cp16(uint32_t dst, const void* src) {
    asm volatile("cp.async.cg.shared.global [%0], [%1], 16;"
                 :: "r"(dst), "l"(src) : "memory");
}
__device__ __forceinline__ void ldsm4(uint32_t* r, uint32_t addr) {
    asm volatile("ldmatrix.sync.aligned.m8n8.x4.shared.b16 {%0,%1,%2,%3}, [%4];"
                 : "=r"(r[0]), "=r"(r[1]), "=r"(r[2]), "=r"(r[3]) : "r"(addr));
}
__device__ __forceinline__ void ldsm4t(uint32_t* r, uint32_t addr) {
    asm volatile("ldmatrix.sync.aligned.m8n8.x4.trans.shared.b16 {%0,%1,%2,%3}, [%4];"
                 : "=r"(r[0]), "=r"(r[1]), "=r"(r[2]), "=r"(r[3]) : "r"(addr));
}
__device__ __forceinline__ void mma16816(float* d, const uint32_t* a,
                                         const uint32_t* b) {
    asm volatile(
        "mma.sync.aligned.m16n8k16.row.col.f32.bf16.bf16.f32 "
        "{%0,%1,%2,%3}, {%4,%5,%6,%7}, {%8,%9}, {%0,%1,%2,%3};"
        : "+f"(d[0]), "+f"(d[1]), "+f"(d[2]), "+f"(d[3])
        : "r"(a[0]), "r"(a[1]), "r"(a[2]), "r"(a[3]), "r"(b[0]), "r"(b[1]));
}

// ---------------- prep: fp32 -> bf16 hi/lo split ---------------------------
__global__ __launch_bounds__(256) void prep_split(const float* __restrict__ x,
                                                  __nv_bfloat16* __restrict__ hi,
                                                  __nv_bfloat16* __restrict__ lo,
                                                  int n4)
{
    int idx = blockIdx.x * blockDim.x + threadIdx.x;
    if (idx >= n4) return;
    float4 v = ((const float4*)x)[idx];
    __nv_bfloat16 h0 = __float2bfloat16(v.x), h1 = __float2bfloat16(v.y);
    __nv_bfloat16 h2 = __float2bfloat16(v.z), h3 = __float2bfloat16(v.w);
    __nv_bfloat162* hp = (__nv_bfloat162*)hi;
    __nv_bfloat162* lp = (__nv_bfloat162*)lo;
    hp[2*idx]   = __nv_bfloat162(h0, h1);
    hp[2*idx+1] = __nv_bfloat162(h2, h3);
    lp[2*idx]   = __nv_bfloat162(__float2bfloat16(v.x - __bfloat162float(h0)),
                                 __float2bfloat16(v.y - __bfloat162float(h1)));
    lp[2*idx+1] = __nv_bfloat162(__float2bfloat16(v.z - __bfloat162float(h2)),
                                 __float2bfloat16(v.w - __bfloat162float(h3)));
}

// ---------------- prep: all 4 weights W[K][N] -> W^T[n][k] bf16 hi/lo ------
__global__ __launch_bounds__(256) void wtrans_all(
    const float* __restrict__ Wq, const float* __restrict__ Wk,
    const float* __restrict__ Wv, const float* __restrict__ Wo,
    __nv_bfloat16* qh, __nv_bfloat16* ql, __nv_bfloat16* kh, __nv_bfloat16* kl,
    __nv_bfloat16* vh, __nv_bfloat16* vl, __nv_bfloat16* oh, __nv_bfloat16* ol)
{
    const float* W; __nv_bfloat16 *th, *tl; int N;
    switch (blockIdx.z) {
        case 0:  W = Wq; th = qh; tl = ql; N = 2048; break;
        case 1:  W = Wk; th = kh; tl = kl; N = 512;  break;
        case 2:  W = Wv; th = vh; tl = vl; N = 512;  break;
        default: W = Wo; th = oh; tl = ol; N = 2048; break;
    }
    int n0 = blockIdx.x * 32, k0 = blockIdx.y * 32;
    if (n0 >= N) return;
    __shared__ float t[32][33];
    int tx = threadIdx.x & 31, ty = threadIdx.x >> 5;
#pragma unroll
    for (int j = 0; j < 32; j += 8)
        t[ty + j][tx] = W[(size_t)(k0 + ty + j) * N + n0 + tx];
    __syncthreads();
#pragma unroll
    for (int j = 0; j < 32; j += 8) {
        float v = t[tx][ty + j];
        __nv_bfloat16 h = __float2bfloat16(v);
        size_t o = (size_t)(n0 + ty + j) * KDIM + k0 + tx;
        th[o] = h;
        tl[o] = __float2bfloat16(v - __bfloat162float(h));
    }
}

// ---------------- mma.sync GEMM: 512 threads, 16 warps (4m x 4n) -----------
// warp tile 32x32; 128x128 CTA tile, K-stage 64, cp.async double-buffered.
template <bool HEAD>
__global__ __launch_bounds__(512)
void gemm_mma(const __nv_bfloat16* __restrict__ Ahi, const __nv_bfloat16* __restrict__ Alo,
              const __nv_bfloat16* __restrict__ Bhi, const __nv_bfloat16* __restrict__ Blo,
              float* __restrict__ C, int Nglob, int Hout)
{
    extern __shared__ __align__(16) char smem[];
    const uint32_t sb0 = cvta_s(smem);

    const int tid  = threadIdx.x;
    const int wid  = tid >> 5, lane = tid & 31;
    const int wm   = wid & 3,  wn   = wid >> 2;        // 4 x 4 warps
    const int am   = wm * 32,  bn0  = wn * 32;
    const int bm   = blockIdx.y * 128, bn = blockIdx.x * 128;

    const __nv_bfloat16* srcs[4] = { Ahi + (size_t)bm * KDIM, Alo + (size_t)bm * KDIM,
                                     Bhi + (size_t)bn * KDIM, Blo + (size_t)bn * KDIM };

    float acc[2][4][4];
#pragma unroll
    for (int mi = 0; mi < 2; mi++)
#pragma unroll
        for (int ni = 0; ni < 4; ni++)
#pragma unroll
            for (int c = 0; c < 4; c++) acc[mi][ni][c] = 0.f;

    const int NT = KDIM / 64;

    auto load_stage = [&](int s, int kt) {
        uint32_t sb = sb0 + s * 65536;
#pragma unroll
        for (int tt = 0; tt < 4; tt++) {
            const __nv_bfloat16* src = srcs[tt];
#pragma unroll
            for (int a = 0; a < 2; a++) {
                int q = tid + a * 512;          // 0..1023 chunks per tile
                int r = q >> 3, c4 = q & 7;
                uint32_t dst = sb + tt * 16384 + r * 128 + ((c4 ^ (r & 7)) << 4);
                cp16(dst, src + (size_t)r * KDIM + kt + c4 * 8);
            }
        }
        asm volatile("cp.async.commit_group;" ::: "memory");
    };

    load_stage(0, 0);

    for (int it = 0; it < NT; ++it) {
        if (it + 1 < NT) {
            load_stage((it + 1) & 1, (it + 1) * 64);
            asm volatile("cp.async.wait_group 1;" ::: "memory");
        } else {
            asm volatile("cp.async.wait_group 0;" ::: "memory");
        }
        __syncthreads();

        const uint32_t sb = sb0 + (it & 1) * 65536;
#pragma unroll
        for (int ks = 0; ks < 4; ks++) {
            uint32_t ah[2][4], al[2][4], bh[4][2], bl[4][2];
#pragma unroll
            for (int mi = 0; mi < 2; mi++) {
                int r  = am + mi * 16 + (lane & 15);
                int c4 = ks * 2 + (lane >> 4);
                uint32_t off = r * 128 + ((c4 ^ (r & 7)) << 4);
                ldsm4(ah[mi], sb + off);
                ldsm4(al[mi], sb + 16384 + off);
            }
#pragma unroll
            for (int nb = 0; nb < 2; nb++) {
                int r  = bn0 + nb * 16 + (lane & 15);
                int c4 = ks * 2 + (lane >> 4);
                uint32_t off = r * 128 + ((c4 ^ (r & 7)) << 4);
                uint32_t t[4];
                ldsm4(t, sb + 32768 + off);
                bh[nb*2][0] = t[0]; bh[nb*2][1] = t[2];
                bh[nb*2+1][0] = t[1]; bh[nb*2+1][1] = t[3];
                ldsm4(t, sb + 49152 + off);
                bl[nb*2][0] = t[0]; bl[nb*2][1] = t[2];
                bl[nb*2+1][0] = t[1]; bl[nb*2+1][1] = t[3];
            }
#pragma unroll
            for (int mi = 0; mi < 2; mi++)
#pragma unroll
                for (int ni = 0; ni < 4; ni++) mma16816(acc[mi][ni], ah[mi], bh[ni]);
#pragma unroll
            for (int mi = 0; mi < 2; mi++)
#pragma unroll
                for (int ni = 0; ni < 4; ni++) mma16816(acc[mi][ni], al[mi], bh[ni]);
#pragma unroll
            for (int mi = 0; mi < 2; mi++)
#pragma unroll
                for (int ni = 0; ni < 4; ni++) mma16816(acc[mi][ni], ah[mi], bl[ni]);
        }
        __syncthreads();
    }

    const int g = lane >> 2, tig = lane & 3;
#pragma unroll
    for (int mi = 0; mi < 2; mi++) {
#pragma unroll
        for (int ni = 0; ni < 4; ni++) {
            int d   = bn0 + ni * 8 + tig * 2;
            int r0  = bm + am + mi * 16 + g;
            int r1  = r0 + 8;
            float* p0;
            float* p1;
            if (HEAD) {
                int h = bn >> 7;
                int b0 = r0 >> 10, n0 = r0 & 1023;
                int b1 = r1 >> 10, n1 = r1 & 1023;
                p0 = C + (((size_t)(b0 * Hout + h)) * NSEQ + n0) * DH + d;
                p1 = C + (((size_t)(b1 * Hout + h)) * NSEQ + n1) * DH + d;
            } else {
                p0 = C + (size_t)r0 * Nglob + bn + d;
                p1 = C + (size_t)r1 * Nglob + bn + d;
            }
            *(float2*)p0 = make_float2(acc[mi][ni][0], acc[mi][ni][1]);
            *(float2*)p1 = make_float2(acc[mi][ni][2], acc[mi][ni][3]);
        }
    }
}

// ---------------- rope table + apply (fp32 -> rotated bf16 hi/lo) ----------
__global__ void rope_table(float* __restrict__ cs)
{
    int idx = blockIdx.x * blockDim.x + threadIdx.x;
    if (idx >= NSEQ * 64) return;
    int i = idx & 63, n = idx >> 6;
    double invf = exp(-(double)i * 0.14391156831212787);
    double ang  = (double)n * invf;
    double s, c;
    sincos(ang, &s, &c);
    cs[idx * 2]     = (float)c;
    cs[idx * 2 + 1] = (float)s;
}
__global__ void rope_hl(const float* __restrict__ src, const float* __restrict__ cs,
                        __nv_bfloat16* __restrict__ hi, __nv_bfloat16* __restrict__ lo,
                        int total)
{
    int idx = blockIdx.x * blockDim.x + threadIdx.x;
    if (idx >= total) return;
    int i   = idx & 63;
    int n   = (idx >> 6) & 1023;
    int bhd = idx >> 16;
    float2 v = ((const float2*)cs)[n * 64 + i];
    size_t o0 = (size_t)bhd * (NSEQ * DH) + n * DH + i;
    float t1 = src[o0], t2 = src[o0 + 64];
    float r0 = t1 * v.x - t2 * v.y;
    float r1 = t2 * v.x + t1 * v.y;
    __nv_bfloat16 b0 = __float2bfloat16(r0);
    __nv_bfloat16 b1 = __float2bfloat16(r1);
    hi[o0]      = b0; lo[o0]      = __float2bfloat16(r0 - __bfloat162float(b0));
    hi[o0 + 64] = b1; lo[o0 + 64] = __float2bfloat16(r1 - __bfloat162float(b1));
}

// ---------------- tensor-core causal flash attention -----------------------
// q-tile 128 x k-tile 64, 8 warps (warp = 16 q-rows), bf16 hi/lo 3-pass.
// smem (224KB): Qhi 0 | Qlo 32K | K stages 64K..128K | V stages 128K..192K
//               | Phi 192K+4K.. -> PH 196608 | PL 212992
__global__ __launch_bounds__(256)
void flash_tc(const __nv_bfloat16* __restrict__ Qh_, const __nv_bfloat16* __restrict__ Ql_,
              const __nv_bfloat16* __restrict__ Kh_, const __nv_bfloat16* __restrict__ Kl_,
              const __nv_bfloat16* __restrict__ Vh_, const __nv_bfloat16* __restrict__ Vl_,
              const float* __restrict__ hsc,
              __nv_bfloat16* __restrict__ Ohi, __nv_bfloat16* __restrict__ Olo)
{
    extern __shared__ __align__(16) char smc[];
    const uint32_t smb = cvta_s(smc);
    const int PH = 196608, PL = 212992;
    const int tid = threadIdx.x, wid = tid >> 5, lane = tid & 31;
    const int qb = 7 - blockIdx.x;                    // big q-blocks first
    const int bh = blockIdx.y, b = bh >> 4, h = bh & 15, kvh = h >> 2;
    const int m0 = wid * 16;
    const int g = lane >> 2, tig = lane & 3;
    const float scale = 0.08838834764831845f;

    const __nv_bfloat16* Qhg = Qh_ + ((size_t)(b * NH + h) * NSEQ + qb * 128) * DH;
    const __nv_bfloat16* Qlg = Ql_ + ((size_t)(b * NH + h) * NSEQ + qb * 128) * DH;
    const size_t kvb = (size_t)(b * NKV + kvh) * NSEQ * DH;

    // Q tiles (hi+lo, 128 rows) via cp.async
#pragma unroll
    for (int t = 0; t < 8; t++) {
        int e = tid + t * 256, r = e >> 4, c4 = e & 15;
        uint32_t off = r * 256 + ((c4 ^ (r & 7)) << 4);
        cp16(smb + off,         Qhg + r * DH + c4 * 8);
        cp16(smb + 32768 + off, Qlg + r * DH + c4 * 8);
    }
    auto ldkv = [&](int s, int kb) {
        const __nv_bfloat16* kh = Kh_ + kvb + (size_t)kb * 64 * DH;
        const __nv_bfloat16* kl = Kl_ + kvb + (size_t)kb * 64 * DH;
        const __nv_bfloat16* vh = Vh_ + kvb + (size_t)kb * 64 * DH;
        const __nv_bfloat16* vl = Vl_ + kvb + (size_t)kb * 64 * DH;
        uint32_t kd = smb + 65536  + s * 32768;
        uint32_t vd = smb + 131072 + s * 32768;
#pragma unroll
        for (int t = 0; t < 4; t++) {
            int e = tid + t * 256, r = e >> 4, c4 = e & 15;
            uint32_t off = r * 256 + ((c4 ^ (r & 7)) << 4);
            int go = r * DH + c4 * 8;
            cp16(kd + off,         kh + go);
            cp16(kd + 16384 + off, kl + go);
            cp16(vd + off,         vh + go);
            cp16(vd + 16384 + off, vl + go);
        }
        asm volatile("cp.async.commit_group;" ::: "memory");
    };
    ldkv(0, 0);   // commits Q + KV0 as one group

    float m_i[2] = {-1e30f, -1e30f}, l_i[2] = {0.f, 0.f};
    float o[16][4];
#pragma unroll
    for (int ni = 0; ni < 16; ni++)
#pragma unroll
        for (int c = 0; c < 4; c++) o[ni][c] = 0.f;

    const int kb_max = 2 * qb + 1;
    for (int kb = 0; kb <= kb_max; ++kb) {
        asm volatile("cp.async.wait_group 0;" ::: "memory");
        __syncthreads();
        if (kb < kb_max) ldkv((kb + 1) & 1, kb + 1);

        const uint32_t sK = smb + 65536  + (kb & 1) * 32768;
        const uint32_t sV = smb + 131072 + (kb & 1) * 32768;

        // ---- S = Q K^T (3-pass hi/lo), warp tile 16x64 ----
        float sf[8][4];
#pragma unroll
        for (int ni = 0; ni < 8; ni++)
#pragma unroll
            for (int c = 0; c < 4; c++) sf[ni][c] = 0.f;

#pragma unroll
        for (int ks = 0; ks < 8; ks++) {
            uint32_t ah[4], al[4], bh2[8][2], bl2[8][2];
            {
                int r = m0 + (lane & 15), c4 = ks * 2 + (lane >> 4);
                uint32_t off = r * 256 + ((c4 ^ (r & 7)) << 4);
                ldsm4(ah, smb + off);
                ldsm4(al, smb + 32768 + off);
            }
#pragma unroll
            for (int nb = 0; nb < 4; nb++) {
                int r = nb * 16 + (lane & 15), c4 = ks * 2 + (lane >> 4);
                uint32_t off = r * 256 + ((c4 ^ (r & 7)) << 4);
                uint32_t t4r[4];
                ldsm4(t4r, sK + off);
                bh2[nb*2][0] = t4r[0]; bh2[nb*2][1] = t4r[2];
                bh2[nb*2+1][0] = t4r[1]; bh2[nb*2+1][1] = t4r[3];
                ldsm4(t4r, sK + 16384 + off);
                bl2[nb*2][0] = t4r[0]; bl2[nb*2][1] = t4r[2];
                bl2[nb*2+1][0] = t4r[1]; bl2[nb*2+1][1] = t4r[3];
            }
#pragma unroll
            for (int ni = 0; ni < 8; ni++) mma16816(sf[ni], ah, bh2[ni]);
#pragma unroll
            for (int ni = 0; ni < 8; ni++) mma16816(sf[ni], al, bh2[ni]);
#pragma unroll
            for (int ni = 0; ni < 8; ni++) mma16816(sf[ni], ah, bl2[ni]);
        }

        // ---- online softmax ----
        const bool near = (kb * 64 + 63) > (qb * 128 + m0);
#pragma unroll
        for (int rr = 0; rr < 2; rr++) {
            int row_g = qb * 128 + m0 + g + rr * 8;
            float mx = -1e30f;
#pragma unroll
            for (int ni = 0; ni < 8; ni++)
#pragma unroll
                for (int c = 0; c < 2; c++) {
                    float v = sf[ni][rr * 2 + c] * scale;
                    if (near && (kb * 64 + ni * 8 + tig * 2 + c) > row_g) v = -1e30f;
                    sf[ni][rr * 2 + c] = v;
                    mx = fmaxf(mx, v);
                }
            mx = fmaxf(mx, __shfl_xor_sync(0xffffffffu, mx, 1));
            mx = fmaxf(mx, __shfl_xor_sync(0xffffffffu, mx, 2));
            float mn    = fmaxf(m_i[rr], mx);
            float alpha = __expf(m_i[rr] - mn);
            m_i[rr] = mn;
            float rs = 0.f;
#pragma unroll
            for (int ni = 0; ni < 8; ni++)
#pragma unroll
                for (int c = 0; c < 2; c++) {
                    float p = __expf(sf[ni][rr * 2 + c] - mn);
                    sf[ni][rr * 2 + c] = p;
                    rs += p;
                }
            rs += __shfl_xor_sync(0xffffffffu, rs, 1);
            rs += __shfl_xor_sync(0xffffffffu, rs, 2);
            l_i[rr] = l_i[rr] * alpha + rs;
#pragma unroll
            for (int ni = 0; ni < 16; ni++) {
                o[ni][rr * 2]     *= alpha;
                o[ni][rr * 2 + 1] *= alpha;
            }
        }

        // ---- store P hi/lo to smem (own warp rows only) ----
        __syncwarp();
#pragma unroll
        for (int ni = 0; ni < 8; ni++)
#pragma unroll
            for (int rr = 0; rr < 2; rr++) {
                int r = m0 + g + rr * 8;
                uint32_t off = r * 128 + ((ni ^ (r & 7)) << 4) + tig * 4;
                float p0 = sf[ni][rr * 2], p1 = sf[ni][rr * 2 + 1];
                __nv_bfloat16 h0 = __float2bfloat16(p0), h1 = __float2bfloat16(p1);
                *(__nv_bfloat162*)(smc + PH + off) = __nv_bfloat162(h0, h1);
                *(__nv_bfloat162*)(smc + PL + off) =
                    __nv_bfloat162(__float2bfloat16(p0 - __bfloat162float(h0)),
                                   __float2bfloat16(p1 - __bfloat162float(h1)));
            }
        __syncwarp();

        // ---- O += P V (3-pass), warp tile 16x128 ----
#pragma unroll
        for (int ks = 0; ks < 4; ks++) {
            uint32_t ph[4], pl[4];
            {
                int r = m0 + (lane & 15), c3 = ks * 2 + (lane >> 4);
                uint32_t off = r * 128 + ((c3 ^ (r & 7)) << 4);
                ldsm4(ph, smb + PH + off);
                ldsm4(pl, smb + PL + off);
            }
#pragma unroll
            for (int nb = 0; nb < 8; nb++) {
                int row = ks * 16 + (lane & 7) + ((lane & 16) >> 1);
                int ch  = nb * 2 + ((lane >> 3) & 1);
                uint32_t off = row * 256 + ((ch ^ (row & 7)) << 4);
                uint32_t t4r[4], bvh[2][2], bvl[2][2];
                ldsm4t(t4r, sV + off);
                bvh[0][0] = t4r[0]; bvh[0][1] = t4r[2];
                bvh[1][0] = t4r[1]; bvh[1][1] = t4r[3];
                ldsm4t(t4r, sV + 16384 + off);
                bvl[0][0] = t4r[0]; bvl[0][1] = t4r[2];
                bvl[1][0] = t4r[1]; bvl[1][1] = t4r[3];
                mma16816(o[nb*2],   ph, bvh[0]);
                mma16816(o[nb*2+1], ph, bvh[1]);
                mma16816(o[nb*2],   pl, bvh[0]);
                mma16816(o[nb*2+1], pl, bvh[1]);
                mma16816(o[nb*2],   ph, bvl[0]);
                mma16816(o[nb*2+1], ph, bvl[1]);
            }
        }
    }

    // ---- epilogue: normalize, head-scale, write bf16 hi/lo O ----
    const float hval = hsc[h];
#pragma unroll
    for (int rr = 0; rr < 2; rr++) {
        float inv = hval / l_i[rr];
        int n = qb * 128 + m0 + g + rr * 8;
        size_t base = ((size_t)(b * NSEQ + n)) * DIMM + h * DH;
#pragma unroll
        for (int ni = 0; ni < 16; ni++) {
            int col = ni * 8 + tig * 2;
            float v0 = o[ni][rr * 2] * inv, v1 = o[ni][rr * 2 + 1] * inv;
            __nv_bfloat16 h0 = __float2bfloat16(v0), h1 = __float2bfloat16(v1);
            *(__nv_bfloat162*)(Ohi + base + col) = __nv_bfloat162(h0, h1);
            *(__nv_bfloat162*)(Olo + base + col) =
                __nv_bfloat162(__float2bfloat16(v0 - __bfloat162float(h0)),
                               __float2bfloat16(v1 - __bfloat162float(h1)));
        }
    }
}

// ---------------- launch ---------------------------------------------------
extern "C" void kernel_launch(void* const* d_in, const int* in_sizes, int n_in,
                              void* d_out, int out_size)
{
    const float* x   = (const float*)d_in[0];
    const float* Wq  = (const float*)d_in[1];
    const float* Wk  = (const float*)d_in[2];
    const float* Wv  = (const float*)d_in[3];
    const float* Wo  = (const float*)d_in[4];
    const float* hsc = (const float*)d_in[5];
    float* out = (float*)d_out;

    float *Qh, *Kh, *Vh, *cs;
    __nv_bfloat16 *xhi, *xlo, *Wqh, *Wql, *Wkh, *Wkl, *Wvh, *Wvl, *Woh, *Wol, *Ohi, *Olo;
    __nv_bfloat16 *Qbh, *Qbl, *Kbh, *Kbl, *Vbh, *Vbl;
    cudaGetSymbolAddress((void**)&Qh,  g_Qh);
    cudaGetSymbolAddress((void**)&Kh,  g_Kh);
    cudaGetSymbolAddress((void**)&Vh,  g_Vh);
    cudaGetSymbolAddress((void**)&cs,  g_cs);
    cudaGetSymbolAddress((void**)&xhi, g_xhi);  cudaGetSymbolAddress((void**)&xlo, g_xlo);
    cudaGetSymbolAddress((void**)&Wqh, g_Wqh);  cudaGetSymbolAddress((void**)&Wql, g_Wql);
    cudaGetSymbolAddress((void**)&Wkh, g_Wkh);  cudaGetSymbolAddress((void**)&Wkl, g_Wkl);
    cudaGetSymbolAddress((void**)&Wvh, g_Wvh);  cudaGetSymbolAddress((void**)&Wvl, g_Wvl);
    cudaGetSymbolAddress((void**)&Woh, g_Woh);  cudaGetSymbolAddress((void**)&Wol, g_Wol);
    cudaGetSymbolAddress((void**)&Ohi, g_Ohi);  cudaGetSymbolAddress((void**)&Olo, g_Olo);
    cudaGetSymbolAddress((void**)&Qbh, g_Qbh);  cudaGetSymbolAddress((void**)&Qbl, g_Qbl);
    cudaGetSymbolAddress((void**)&Kbh, g_Kbh);  cudaGetSymbolAddress((void**)&Kbl, g_Kbl);
    cudaGetSymbolAddress((void**)&Vbh, g_Vbh);  cudaGetSymbolAddress((void**)&Vbl, g_Vbl);

    // 1..3: prep  (launch order: ncu -s 5 -c 1 captures launch #6 = gemmQ)
    rope_table<<<(NSEQ * 64 + 255) / 256, 256>>>(cs);
    prep_split<<<(MTOT * KDIM / 4 + 255) / 256, 256>>>(x, xhi, xlo, MTOT * KDIM / 4);
    wtrans_all<<<dim3(64, 64, 4), 256>>>(Wq, Wk, Wv, Wo, Wqh, Wql, Wkh, Wkl,
                                         Wvh, Wvl, Woh, Wol);

    // 4..6: projections (Q last so it is the profiled launch)
    const int gsm = 131072;
    cudaFuncSetAttribute(gemm_mma<true>,  cudaFuncAttributeMaxDynamicSharedMemorySize, gsm);
    cudaFuncSetAttribute(gemm_mma<false>, cudaFuncAttributeMaxDynamicSharedMemorySize, gsm);
    gemm_mma<true><<<dim3(4,  32), 512, gsm>>>(xhi, xlo, Wkh, Wkl, Kh, 512,  NKV);
    gemm_mma<true><<<dim3(4,  32), 512, gsm>>>(xhi, xlo, Wvh, Wvl, Vh, 512,  NKV);
    gemm_mma<true><<<dim3(16, 32), 512, gsm>>>(xhi, xlo, Wqh, Wql, Qh, 2048, NH);

    // 7..9: rope -> bf16 hi/lo, V split
    int ropeQ = NH  * B_SZ * NSEQ * 64;
    int ropeK = NKV * B_SZ * NSEQ * 64;
    rope_hl<<<ropeQ / 256, 256>>>(Qh, cs, Qbh, Qbl, ropeQ);
    rope_hl<<<ropeK / 256, 256>>>(Kh, cs, Kbh, Kbl, ropeK);
    prep_split<<<(B_SZ * NKV * NSEQ * DH / 4 + 255) / 256, 256>>>(
        Vh, Vbh, Vbl, B_SZ * NKV * NSEQ * DH / 4);

    // 10: tensor-core flash attention (q-tile 128, 8 warps, 224KB smem)
    const int fsm = 229376;
    cudaFuncSetAttribute(flash_tc, cudaFuncAttributeMaxDynamicSharedMemorySize, fsm);
    flash_tc<<<dim3(8, B_SZ * NH), 256, fsm>>>(Qbh, Qbl, Kbh, Kbl, Vbh, Vbl,
                                               hsc, Ohi, Olo);

    // 11: output projection
    gemm_mma<false><<<dim3(16, 32), 512, gsm>>>(Ohi, Olo, Woh, Wol, out, 2048, 0);
}

// round 11
// speedup vs baseline: 1.0594x; 1.0594x over previous
#include <cuda_runtime.h>
#include <cuda_bf16.h>
#include <math.h>
#include <stdint.h>

#define B_SZ  4
#define NSEQ  1024
#define DIMM  2048
#define KDIM  2048
#define NH    16
#define NKV   4
#define DH    128
#define MTOT  (B_SZ * NSEQ)

// ---------------- scratch (device globals: no allocation allowed) ----------
__device__ float g_Qh[B_SZ * NH  * NSEQ * DH];     // fp32 [b,h,n,d]
__device__ float g_Kh[B_SZ * NKV * NSEQ * DH];
__device__ float g_Vh[B_SZ * NKV * NSEQ * DH];
__device__ __nv_bfloat16 g_xhi[MTOT * KDIM], g_xlo[MTOT * KDIM];
__device__ __nv_bfloat16 g_Wqh[2048 * KDIM], g_Wql[2048 * KDIM];   // W^T [n][k]
__device__ __nv_bfloat16 g_Wkh[512  * KDIM], g_Wkl[512  * KDIM];
__device__ __nv_bfloat16 g_Wvh[512  * KDIM], g_Wvl[512  * KDIM];
__device__ __nv_bfloat16 g_Woh[2048 * KDIM], g_Wol[2048 * KDIM];
__device__ __nv_bfloat16 g_Ohi[MTOT * DIMM], g_Olo[MTOT * DIMM];
__device__ __nv_bfloat16 g_Qbh[B_SZ * NH  * NSEQ * DH], g_Qbl[B_SZ * NH  * NSEQ * DH];
__device__ __nv_bfloat16 g_Kbh[B_SZ * NKV * NSEQ * DH], g_Kbl[B_SZ * NKV * NSEQ * DH];
__device__ __nv_bfloat16 g_Vbh[B_SZ * NKV * NSEQ * DH], g_Vbl[B_SZ * NKV * NSEQ * DH];
__device__ float g_cs[NSEQ * 64 * 2];              // rope cos/sin table

// ---------------- helpers ---------------------------------------------------
__device__ __forceinline__ uint32_t cvta_s(const void* p) {
    uint32_t a;
    asm("{ .reg .u64 t; cvta.to.shared.u64 t, %1; cvt.u32.u64 %0, t; }"
        : "=r"(a) : "l"(p));
    return a;
}
__device__ __forceinline__ void cp16(uint32_t dst, const void* src) {
    asm volatile("cp.async.cg.shared.global [%0], [%1], 16;"
                 :: "r"(dst), "l"(src) : "memory");
}
__device__ __forceinline__ void ldsm4(uint32_t* r, uint32_t addr) {
    asm volatile("ldmatrix.sync.aligned.m8n8.x4.shared.b16 {%0,%1,%2,%3}, [%4];"
                 : "=r"(r[0]), "=r"(r[1]), "=r"(r[2]), "=r"(r[3]) : "r"(addr));
}
__device__ __forceinline__ void ldsm4t(uint32_t* r, uint32_t addr) {
    asm volatile("ldmatrix.sync.aligned.m8n8.x4.trans.shared.b16 {%0,%1,%2,%3}, [%4];"
                 : "=r"(r[0]), "=r"(r[1]), "=r"(r[2]), "=r"(r[3]) : "r"(addr));
}
__device__ __forceinline__ void mma16816(float* d, const uint32_t* a,
                                         const uint32_t* b) {
    asm volatile(
        "mma.sync.aligned.m16n8k16.row.col.f32.bf16.bf16.f32 "
        "{%0,%1,%2,%3}, {%4,%5,%6,%7}, {%8,%9}, {%0,%1,%2,%3};"
        : "+f"(d[0]), "+f"(d[1]), "+f"(d[2]), "+f"(d[3])
        : "r"(a[0]), "r"(a[1]), "r"(a[2]), "r"(a[3]), "r"(b[0]), "r"(b[1]));
}
// pack two floats -> bf16x2 (v0 in low half) + bf16x2 of residuals
__device__ __forceinline__ void pack_hl(float v0, float v1,
                                        uint32_t& hi2, uint32_t& lo2) {
    __nv_bfloat16 h0 = __float2bfloat16(v0), h1 = __float2bfloat16(v1);
    __nv_bfloat162 hp(h0, h1);
    hi2 = *reinterpret_cast<uint32_t*>(&hp);
    __nv_bfloat162 lp(__float2bfloat16(v0 - __bfloat162float(h0)),
                      __float2bfloat16(v1 - __bfloat162float(h1)));
    lo2 = *reinterpret_cast<uint32_t*>(&lp);
}

// ---------------- prep_all: rope table + x split + 4x wtrans (one launch) --
__global__ __launch_bounds__(256) void prep_all(
    const float* __restrict__ x,
    const float* __restrict__ Wq, const float* __restrict__ Wk,
    const float* __restrict__ Wv, const float* __restrict__ Wo,
    float* __restrict__ cs,
    __nv_bfloat16* __restrict__ xhi, __nv_bfloat16* __restrict__ xlo,
    __nv_bfloat16* qh, __nv_bfloat16* ql, __nv_bfloat16* kh, __nv_bfloat16* kl,
    __nv_bfloat16* vh, __nv_bfloat16* vl, __nv_bfloat16* oh, __nv_bfloat16* ol)
{
    const int blk = blockIdx.x, tid = threadIdx.x;
    if (blk < 256) {                       // rope table (65536 entries)
        int idx = blk * 256 + tid;
        int i = idx & 63, n = idx >> 6;
        double invf = exp(-(double)i * 0.14391156831212787);
        double s, c;
        sincos((double)n * invf, &s, &c);
        cs[idx * 2]     = (float)c;
        cs[idx * 2 + 1] = (float)s;
        return;
    }
    if (blk < 8448) {                      // x hi/lo split (2M float4)
        int idx = (blk - 256) * 256 + tid;
        float4 v = ((const float4*)x)[idx];
        __nv_bfloat16 h0 = __float2bfloat16(v.x), h1 = __float2bfloat16(v.y);
        __nv_bfloat16 h2 = __float2bfloat16(v.z), h3 = __float2bfloat16(v.w);
        __nv_bfloat162* hp = (__nv_bfloat162*)xhi;
        __nv_bfloat162* lp = (__nv_bfloat162*)xlo;
        hp[2*idx]   = __nv_bfloat162(h0, h1);
        hp[2*idx+1] = __nv_bfloat162(h2, h3);
        lp[2*idx]   = __nv_bfloat162(__float2bfloat16(v.x - __bfloat162float(h0)),
                                     __float2bfloat16(v.y - __bfloat162float(h1)));
        lp[2*idx+1] = __nv_bfloat162(__float2bfloat16(v.z - __bfloat162float(h2)),
                                     __float2bfloat16(v.w - __bfloat162float(h3)));
        return;
    }
    // weight transposes
    const float* W; __nv_bfloat16 *th, *tl; int N, bi, nb;
    if      (blk < 12544) { W = Wq; th = qh; tl = ql; N = 2048; bi = blk - 8448;  nb = 64; }
    else if (blk < 13568) { W = Wk; th = kh; tl = kl; N = 512;  bi = blk - 12544; nb = 16; }
    else if (blk < 14592) { W = Wv; th = vh; tl = vl; N = 512;  bi = blk - 13568; nb = 16; }
    else                  { W = Wo; th = oh; tl = ol; N = 2048; bi = blk - 14592; nb = 64; }
    int n0 = (bi % nb) * 32, k0 = (bi / nb) * 32;
    __shared__ float t[32][33];
    int tx = tid & 31, ty = tid >> 5;
#pragma unroll
    for (int j = 0; j < 32; j += 8)
        t[ty + j][tx] = W[(size_t)(k0 + ty + j) * N + n0 + tx];
    __syncthreads();
#pragma unroll
    for (int j = 0; j < 32; j += 8) {
        float v = t[tx][ty + j];
        __nv_bfloat16 h = __float2bfloat16(v);
        size_t o = (size_t)(n0 + ty + j) * KDIM + k0 + tx;
        th[o] = h;
        tl[o] = __float2bfloat16(v - __bfloat162float(h));
    }
}

// ---------------- post_all: ropeQ + ropeK + V split (one launch) -----------
__global__ __launch_bounds__(256) void post_all(
    const float* __restrict__ Qh, const float* __restrict__ Kh,
    const float* __restrict__ Vh, const float* __restrict__ cs,
    __nv_bfloat16* __restrict__ Qbh, __nv_bfloat16* __restrict__ Qbl,
    __nv_bfloat16* __restrict__ Kbh, __nv_bfloat16* __restrict__ Kbl,
    __nv_bfloat16* __restrict__ Vbh, __nv_bfloat16* __restrict__ Vbl)
{
    const int blk = blockIdx.x, tid = threadIdx.x;
    if (blk < 20480) {                    // rope on Q (16384 blks) then K (4096)
        const float* src; __nv_bfloat16 *hi, *lo; int idx;
        if (blk < 16384) { src = Qh; hi = Qbh; lo = Qbl; idx = blk * 256 + tid; }
        else             { src = Kh; hi = Kbh; lo = Kbl; idx = (blk - 16384) * 256 + tid; }
        int i   = idx & 63;
        int n   = (idx >> 6) & 1023;
        int bhd = idx >> 16;
        float2 v = ((const float2*)cs)[n * 64 + i];
        size_t o0 = (size_t)bhd * (NSEQ * DH) + n * DH + i;
        float t1 = src[o0], t2 = src[o0 + 64];
        float r0 = t1 * v.x - t2 * v.y;
        float r1 = t2 * v.x + t1 * v.y;
        __nv_bfloat16 b0 = __float2bfloat16(r0);
        __nv_bfloat16 b1 = __float2bfloat16(r1);
        hi[o0]      = b0; lo[o0]      = __float2bfloat16(r0 - __bfloat162float(b0));
        hi[o0 + 64] = b1; lo[o0 + 64] = __float2bfloat16(r1 - __bfloat162float(b1));
        return;
    }
    int idx = (blk - 20480) * 256 + tid;  // V split (2048 blks of float4)
    float4 v = ((const float4*)Vh)[idx];
    __nv_bfloat16 h0 = __float2bfloat16(v.x), h1 = __float2bfloat16(v.y);
    __nv_bfloat16 h2 = __float2bfloat16(v.z), h3 = __float2bfloat16(v.w);
    __nv_bfloat162* hp = (__nv_bfloat162*)Vbh;
    __nv_bfloat162* lp = (__nv_bfloat162*)Vbl;
    hp[2*idx]   = __nv_bfloat162(h0, h1);
    hp[2*idx+1] = __nv_bfloat162(h2, h3);
    lp[2*idx]   = __nv_bfloat162(__float2bfloat16(v.x - __bfloat162float(h0)),
                                 __float2bfloat16(v.y - __bfloat162float(h1)));
    lp[2*idx+1] = __nv_bfloat162(__float2bfloat16(v.z - __bfloat162float(h2)),
                                 __float2bfloat16(v.w - __bfloat162float(h3)));
}

// ---------------- mma.sync GEMM (R9-proven: 256 thr, 8 warps 4m x 2n) ------
template <bool HEAD>
__global__ __launch_bounds__(256)
void gemm_mma(const __nv_bfloat16* __restrict__ Ahi, const __nv_bfloat16* __restrict__ Alo,
              const __nv_bfloat16* __restrict__ Bhi, const __nv_bfloat16* __restrict__ Blo,
              float* __restrict__ C, int Nglob, int Hout)
{
    extern __shared__ __align__(16) char smem[];
    const uint32_t sb0 = cvta_s(smem);

    const int tid  = threadIdx.x;
    const int wid  = tid >> 5, lane = tid & 31;
    const int wm   = wid & 3,  wn   = wid >> 2;
    const int am   = wm * 32,  bn0  = wn * 64;
    const int bm   = blockIdx.y * 128, bn = blockIdx.x * 128;

    const __nv_bfloat16* srcs[4] = { Ahi + (size_t)bm * KDIM, Alo + (size_t)bm * KDIM,
                                     Bhi + (size_t)bn * KDIM, Blo + (size_t)bn * KDIM };

    const int lr[4] = { (tid + 0)   >> 3, (tid + 256) >> 3,
                        (tid + 512) >> 3, (tid + 768) >> 3 };
    const int lc[4] = { (tid + 0)   & 7,  (tid + 256) & 7,
                        (tid + 512) & 7,  (tid + 768) & 7 };

    float acc[2][8][4];
#pragma unroll
    for (int mi = 0; mi < 2; mi++)
#pragma unroll
        for (int ni = 0; ni < 8; ni++)
#pragma unroll
            for (int c = 0; c < 4; c++) acc[mi][ni][c] = 0.f;

    const int NT = KDIM / 64;

    auto load_stage = [&](int s, int kt) {
        uint32_t sb = sb0 + s * 65536;
#pragma unroll
        for (int tt = 0; tt < 4; tt++) {
            const __nv_bfloat16* src = srcs[tt];
#pragma unroll
            for (int a = 0; a < 4; a++) {
                int r = lr[a], c4 = lc[a];
                uint32_t dst = sb + tt * 16384 + r * 128 + ((c4 ^ (r & 7)) << 4);
                cp16(dst, src + (size_t)r * KDIM + kt + c4 * 8);
            }
        }
        asm volatile("cp.async.commit_group;" ::: "memory");
    };

    load_stage(0, 0);

    for (int it = 0; it < NT; ++it) {
        if (it + 1 < NT) {
            load_stage((it + 1) & 1, (it + 1) * 64);
            asm volatile("cp.async.wait_group 1;" ::: "memory");
        } else {
            asm volatile("cp.async.wait_group 0;" ::: "memory");
        }
        __syncthreads();

        const uint32_t sb = sb0 + (it & 1) * 65536;
#pragma unroll
        for (int ks = 0; ks < 4; ks++) {
            uint32_t ah[2][4], al[2][4], bh[8][2], bl[8][2];
#pragma unroll
            for (int mi = 0; mi < 2; mi++) {
                int r  = am + mi * 16 + (lane & 15);
                int c4 = ks * 2 + (lane >> 4);
                uint32_t off = r * 128 + ((c4 ^ (r & 7)) << 4);
                ldsm4(ah[mi], sb + off);
                ldsm4(al[mi], sb + 16384 + off);
            }
#pragma unroll
            for (int nb = 0; nb < 4; nb++) {
                int r  = bn0 + nb * 16 + (lane & 15);
                int c4 = ks * 2 + (lane >> 4);
                uint32_t off = r * 128 + ((c4 ^ (r & 7)) << 4);
                uint32_t t[4];
                ldsm4(t, sb + 32768 + off);
                bh[nb*2][0] = t[0]; bh[nb*2][1] = t[2];
                bh[nb*2+1][0] = t[1]; bh[nb*2+1][1] = t[3];
                ldsm4(t, sb + 49152 + off);
                bl[nb*2][0] = t[0]; bl[nb*2][1] = t[2];
                bl[nb*2+1][0] = t[1]; bl[nb*2+1][1] = t[3];
            }
#pragma unroll
            for (int mi = 0; mi < 2; mi++)
#pragma unroll
                for (int ni = 0; ni < 8; ni++) mma16816(acc[mi][ni], ah[mi], bh[ni]);
#pragma unroll
            for (int mi = 0; mi < 2; mi++)
#pragma unroll
                for (int ni = 0; ni < 8; ni++) mma16816(acc[mi][ni], al[mi], bh[ni]);
#pragma unroll
            for (int mi = 0; mi < 2; mi++)
#pragma unroll
                for (int ni = 0; ni < 8; ni++) mma16816(acc[mi][ni], ah[mi], bl[ni]);
        }
        __syncthreads();
    }

    const int g = lane >> 2, tig = lane & 3;
#pragma unroll
    for (int mi = 0; mi < 2; mi++) {
#pragma unroll
        for (int ni = 0; ni < 8; ni++) {
            int d   = bn0 + ni * 8 + tig * 2;
            int r0  = bm + am + mi * 16 + g;
            int r1  = r0 + 8;
            float* p0;
            float* p1;
            if (HEAD) {
                int h = bn >> 7;
                int b0 = r0 >> 10, n0 = r0 & 1023;
                int b1 = r1 >> 10, n1 = r1 & 1023;
                p0 = C + (((size_t)(b0 * Hout + h)) * NSEQ + n0) * DH + d;
                p1 = C + (((size_t)(b1 * Hout + h)) * NSEQ + n1) * DH + d;
            } else {
                p0 = C + (size_t)r0 * Nglob + bn + d;
                p1 = C + (size_t)r1 * Nglob + bn + d;
            }
            *(float2*)p0 = make_float2(acc[mi][ni][0], acc[mi][ni][1]);
            *(float2*)p1 = make_float2(acc[mi][ni][2], acc[mi][ni][3]);
        }
    }
}

// ---------------- tensor-core causal flash attention, P in registers -------
// q-tile 128 x kv-tile 64, 8 warps (warp = 16 q-rows).
// smem (192KB): Qhi 0 | Qlo 32K | K stages 64K..128K | V stages 128K..192K
__global__ __launch_bounds__(256)
void flash_tc(const __nv_bfloat16* __restrict__ Qh_, const __nv_bfloat16* __restrict__ Ql_,
              const __nv_bfloat16* __restrict__ Kh_, const __nv_bfloat16* __restrict__ Kl_,
              const __nv_bfloat16* __restrict__ Vh_, const __nv_bfloat16* __restrict__ Vl_,
              const float* __restrict__ hsc,
              __nv_bfloat16* __restrict__ Ohi, __nv_bfloat16* __restrict__ Olo)
{
    extern __shared__ __align__(16) char smc[];
    const uint32_t smb = cvta_s(smc);
    const int tid = threadIdx.x, wid = tid >> 5, lane = tid & 31;
    const int qb = 7 - blockIdx.x;                    // big q-blocks first
    const int bh = blockIdx.y, b = bh >> 4, h = bh & 15, kvh = h >> 2;
    const int m0 = wid * 16;
    const int g = lane >> 2, tig = lane & 3;
    const float scale = 0.08838834764831845f;

    const __nv_bfloat16* Qhg = Qh_ + ((size_t)(b * NH + h) * NSEQ + qb * 128) * DH;
    const __nv_bfloat16* Qlg = Ql_ + ((size_t)(b * NH + h) * NSEQ + qb * 128) * DH;
    const size_t kvb = (size_t)(b * NKV + kvh) * NSEQ * DH;

#pragma unroll
    for (int t = 0; t < 8; t++) {
        int e = tid + t * 256, r = e >> 4, c4 = e & 15;
        uint32_t off = r * 256 + ((c4 ^ (r & 7)) << 4);
        cp16(smb + off,         Qhg + r * DH + c4 * 8);
        cp16(smb + 32768 + off, Qlg + r * DH + c4 * 8);
    }
    auto ldkv = [&](int s, int kb) {
        const __nv_bfloat16* kh = Kh_ + kvb + (size_t)kb * 64 * DH;
        const __nv_bfloat16* kl = Kl_ + kvb + (size_t)kb * 64 * DH;
        const __nv_bfloat16* vh = Vh_ + kvb + (size_t)kb * 64 * DH;
        const __nv_bfloat16* vl = Vl_ + kvb + (size_t)kb * 64 * DH;
        uint32_t kd = smb + 65536  + s * 32768;
        uint32_t vd = smb + 131072 + s * 32768;
#pragma unroll
        for (int t = 0; t < 4; t++) {
            int e = tid + t * 256, r = e >> 4, c4 = e & 15;
            uint32_t off = r * 256 + ((c4 ^ (r & 7)) << 4);
            int go = r * DH + c4 * 8;
            cp16(kd + off,         kh + go);
            cp16(kd + 16384 + off, kl + go);
            cp16(vd + off,         vh + go);
            cp16(vd + 16384 + off, vl + go);
        }
        asm volatile("cp.async.commit_group;" ::: "memory");
    };
    ldkv(0, 0);

    float m_i[2] = {-1e30f, -1e30f}, l_i[2] = {0.f, 0.f};
    float o[16][4];
#pragma unroll
    for (int ni = 0; ni < 16; ni++)
#pragma unroll
        for (int c = 0; c < 4; c++) o[ni][c] = 0.f;

    const int kb_max = 2 * qb + 1;
    for (int kb = 0; kb <= kb_max; ++kb) {
        asm volatile("cp.async.wait_group 0;" ::: "memory");
        __syncthreads();
        if (kb < kb_max) ldkv((kb + 1) & 1, kb + 1);

        const uint32_t sK = smb + 65536  + (kb & 1) * 32768;
        const uint32_t sV = smb + 131072 + (kb & 1) * 32768;

        // ---- S = Q K^T (3-pass hi/lo), warp tile 16x64 ----
        float sf[8][4];
#pragma unroll
        for (int ni = 0; ni < 8; ni++)
#pragma unroll
            for (int c = 0; c < 4; c++) sf[ni][c] = 0.f;

#pragma unroll
        for (int ks = 0; ks < 8; ks++) {
            uint32_t ah[4], al[4], bh2[8][2], bl2[8][2];
            {
                int r = m0 + (lane & 15), c4 = ks * 2 + (lane >> 4);
                uint32_t off = r * 256 + ((c4 ^ (r & 7)) << 4);
                ldsm4(ah, smb + off);
                ldsm4(al, smb + 32768 + off);
            }
#pragma unroll
            for (int nb = 0; nb < 4; nb++) {
                int r = nb * 16 + (lane & 15), c4 = ks * 2 + (lane >> 4);
                uint32_t off = r * 256 + ((c4 ^ (r & 7)) << 4);
                uint32_t t4r[4];
                ldsm4(t4r, sK + off);
                bh2[nb*2][0] = t4r[0]; bh2[nb*2][1] = t4r[2];
                bh2[nb*2+1][0] = t4r[1]; bh2[nb*2+1][1] = t4r[3];
                ldsm4(t4r, sK + 16384 + off);
                bl2[nb*2][0] = t4r[0]; bl2[nb*2][1] = t4r[2];
                bl2[nb*2+1][0] = t4r[1]; bl2[nb*2+1][1] = t4r[3];
            }
#pragma unroll
            for (int ni = 0; ni < 8; ni++) mma16816(sf[ni], ah, bh2[ni]);
#pragma unroll
            for (int ni = 0; ni < 8; ni++) mma16816(sf[ni], al, bh2[ni]);
#pragma unroll
            for (int ni = 0; ni < 8; ni++) mma16816(sf[ni], ah, bl2[ni]);
        }

        // ---- online softmax ----
        const bool near = (kb * 64 + 63) > (qb * 128 + m0);
#pragma unroll
        for (int rr = 0; rr < 2; rr++) {
            int row_g = qb * 128 + m0 + g + rr * 8;
            float mx = -1e30f;
#pragma unroll
            for (int ni = 0; ni < 8; ni++)
#pragma unroll
                for (int c = 0; c < 2; c++) {
                    float v = sf[ni][rr * 2 + c] * scale;
                    if (near && (kb * 64 + ni * 8 + tig * 2 + c) > row_g) v = -1e30f;
                    sf[ni][rr * 2 + c] = v;
                    mx = fmaxf(mx, v);
                }
            mx = fmaxf(mx, __shfl_xor_sync(0xffffffffu, mx, 1));
            mx = fmaxf(mx, __shfl_xor_sync(0xffffffffu, mx, 2));
            float mn    = fmaxf(m_i[rr], mx);
            float alpha = __expf(m_i[rr] - mn);
            m_i[rr] = mn;
            float rs = 0.f;
#pragma unroll
            for (int ni = 0; ni < 8; ni++)
#pragma unroll
                for (int c = 0; c < 2; c++) {
                    float p = __expf(sf[ni][rr * 2 + c] - mn);
                    sf[ni][rr * 2 + c] = p;
                    rs += p;
                }
            rs += __shfl_xor_sync(0xffffffffu, rs, 1);
            rs += __shfl_xor_sync(0xffffffffu, rs, 2);
            l_i[rr] = l_i[rr] * alpha + rs;
#pragma unroll
            for (int ni = 0; ni < 16; ni++) {
                o[ni][rr * 2]     *= alpha;
                o[ni][rr * 2 + 1] *= alpha;
            }
        }

        // ---- O += P V, P converted in-register (no smem roundtrip) ----
        // A-frag for k16 chunk ks: a0,a1 from S n-tile 2ks (c01, c23);
        //                          a2,a3 from S n-tile 2ks+1.
#pragma unroll
        for (int ks = 0; ks < 4; ks++) {
            uint32_t ph[4], pl[4];
            pack_hl(sf[2*ks][0],   sf[2*ks][1],   ph[0], pl[0]);
            pack_hl(sf[2*ks][2],   sf[2*ks][3],   ph[1], pl[1]);
            pack_hl(sf[2*ks+1][0], sf[2*ks+1][1], ph[2], pl[2]);
            pack_hl(sf[2*ks+1][2], sf[2*ks+1][3], ph[3], pl[3]);
#pragma unroll
            for (int nb = 0; nb < 8; nb++) {
                int row = ks * 16 + (lane & 7) + ((lane & 16) >> 1);
                int ch  = nb * 2 + ((lane >> 3) & 1);
                uint32_t off = row * 256 + ((ch ^ (row & 7)) << 4);
                uint32_t t4r[4], bvh[2][2], bvl[2][2];
                ldsm4t(t4r, sV + off);
                bvh[0][0] = t4r[0]; bvh[0][1] = t4r[2];
                bvh[1][0] = t4r[1]; bvh[1][1] = t4r[3];
                ldsm4t(t4r, sV + 16384 + off);
                bvl[0][0] = t4r[0]; bvl[0][1] = t4r[2];
                bvl[1][0] = t4r[1]; bvl[1][1] = t4r[3];
                mma16816(o[nb*2],   ph, bvh[0]);
                mma16816(o[nb*2+1], ph, bvh[1]);
                mma16816(o[nb*2],   pl, bvh[0]);
                mma16816(o[nb*2+1], pl, bvh[1]);
                mma16816(o[nb*2],   ph, bvl[0]);
                mma16816(o[nb*2+1], ph, bvl[1]);
            }
        }
    }

    // ---- epilogue ----
    const float hval = hsc[h];
#pragma unroll
    for (int rr = 0; rr < 2; rr++) {
        float inv = hval / l_i[rr];
        int n = qb * 128 + m0 + g + rr * 8;
        size_t base = ((size_t)(b * NSEQ + n)) * DIMM + h * DH;
#pragma unroll
        for (int ni = 0; ni < 16; ni++) {
            int col = ni * 8 + tig * 2;
            float v0 = o[ni][rr * 2] * inv, v1 = o[ni][rr * 2 + 1] * inv;
            __nv_bfloat16 h0 = __float2bfloat16(v0), h1 = __float2bfloat16(v1);
            *(__nv_bfloat162*)(Ohi + base + col) = __nv_bfloat162(h0, h1);
            *(__nv_bfloat162*)(Olo + base + col) =
                __nv_bfloat162(__float2bfloat16(v0 - __bfloat162float(h0)),
                               __float2bfloat16(v1 - __bfloat162float(h1)));
        }
    }
}

// ---------------- launch ---------------------------------------------------
extern "C" void kernel_launch(void* const* d_in, const int* in_sizes, int n_in,
                              void* d_out, int out_size)
{
    const float* x   = (const float*)d_in[0];
    const float* Wq  = (const float*)d_in[1];
    const float* Wk  = (const float*)d_in[2];
    const float* Wv  = (const float*)d_in[3];
    const float* Wo  = (const float*)d_in[4];
    const float* hsc = (const float*)d_in[5];
    float* out = (float*)d_out;

    float *Qh, *Kh, *Vh, *cs;
    __nv_bfloat16 *xhi, *xlo, *Wqh, *Wql, *Wkh, *Wkl, *Wvh, *Wvl, *Woh, *Wol, *Ohi, *Olo;
    __nv_bfloat16 *Qbh, *Qbl, *Kbh, *Kbl, *Vbh, *Vbl;
    cudaGetSymbolAddress((void**)&Qh,  g_Qh);
    cudaGetSymbolAddress((void**)&Kh,  g_Kh);
    cudaGetSymbolAddress((void**)&Vh,  g_Vh);
    cudaGetSymbolAddress((void**)&cs,  g_cs);
    cudaGetSymbolAddress((void**)&xhi, g_xhi);  cudaGetSymbolAddress((void**)&xlo, g_xlo);
    cudaGetSymbolAddress((void**)&Wqh, g_Wqh);  cudaGetSymbolAddress((void**)&Wql, g_Wql);
    cudaGetSymbolAddress((void**)&Wkh, g_Wkh);  cudaGetSymbolAddress((void**)&Wkl, g_Wkl);
    cudaGetSymbolAddress((void**)&Wvh, g_Wvh);  cudaGetSymbolAddress((void**)&Wvl, g_Wvl);
    cudaGetSymbolAddress((void**)&Woh, g_Woh);  cudaGetSymbolAddress((void**)&Wol, g_Wol);
    cudaGetSymbolAddress((void**)&Ohi, g_Ohi);  cudaGetSymbolAddress((void**)&Olo, g_Olo);
    cudaGetSymbolAddress((void**)&Qbh, g_Qbh);  cudaGetSymbolAddress((void**)&Qbl, g_Qbl);
    cudaGetSymbolAddress((void**)&Kbh, g_Kbh);  cudaGetSymbolAddress((void**)&Kbl, g_Kbl);
    cudaGetSymbolAddress((void**)&Vbh, g_Vbh);  cudaGetSymbolAddress((void**)&Vbl, g_Vbl);

    // launch 1: all prep (rope table + x split + 4 weight transposes)
    prep_all<<<18688, 256>>>(x, Wq, Wk, Wv, Wo, cs, xhi, xlo,
                             Wqh, Wql, Wkh, Wkl, Wvh, Wvl, Woh, Wol);

    // launches 2..4: projections
    const int gsm = 131072;
    cudaFuncSetAttribute(gemm_mma<true>,  cudaFuncAttributeMaxDynamicSharedMemorySize, gsm);
    cudaFuncSetAttribute(gemm_mma<false>, cudaFuncAttributeMaxDynamicSharedMemorySize, gsm);
    gemm_mma<true><<<dim3(4,  32), 256, gsm>>>(xhi, xlo, Wkh, Wkl, Kh, 512,  NKV);
    gemm_mma<true><<<dim3(4,  32), 256, gsm>>>(xhi, xlo, Wvh, Wvl, Vh, 512,  NKV);
    gemm_mma<true><<<dim3(16, 32), 256, gsm>>>(xhi, xlo, Wqh, Wql, Qh, 2048, NH);

    // launch 5: rope Q/K + V split
    post_all<<<22528, 256>>>(Qh, Kh, Vh, cs, Qbh, Qbl, Kbh, Kbl, Vbh, Vbl);

    // launch 6 (PROFILED): tensor-core flash attention, P in registers
    const int fsm = 196608;
    cudaFuncSetAttribute(flash_tc, cudaFuncAttributeMaxDynamicSharedMemorySize, fsm);
    flash_tc<<<dim3(8, B_SZ * NH), 256, fsm>>>(Qbh, Qbl, Kbh, Kbl, Vbh, Vbl,
                                               hsc, Ohi, Olo);

    // launch 7: output projection
    gemm_mma<false><<<dim3(16, 32), 256, gsm>>>(Ohi, Olo, Woh, Wol, out, 2048, 0);
}